// round 13
// baseline (speedup 1.0000x reference)
#include <cuda_runtime.h>
#include <cuda_bf16.h>

#define BMAX 256

// scratch
__device__ float g_p1t [BMAX * 14 * 14 * 32];    // (b, h, w, c) channel-last
__device__ float g_w2m [36 * 8 * 32 * 2];        // mma B-fragment order, tf32-rounded
__device__ float g_ow2s[288 * 24];               // [k=tt*32+ci][sub*12+j], c=2j+sub
__device__ float g_p2  [BMAX * 64 * 7 * 7];      // (b, c, h, w)
__device__ int4   g_recI[BMAX * 196 * 9];        // 4 IMAGE-LOCAL clamped gather offsets
__device__ float4 g_recW[BMAX * 196 * 9];        // 4 bilinear weights (0 if invalid)

__device__ __forceinline__ float corner(const float* __restrict__ p,
                                        int y, int x, int H, int W, int stride) {
    bool v = (y >= 0) & (y < H) & (x >= 0) & (x < W);
    int yc = min(max(y, 0), H - 1);
    int xc = min(max(x, 0), W - 1);
    return v ? p[(yc * W + xc) * stride] : 0.f;
}

__device__ __forceinline__ unsigned tf32r(float x) {
    unsigned u;
    asm("cvt.rna.tf32.f32 %0, %1;" : "=r"(u) : "f"(x));
    return u;
}

__device__ __forceinline__ void mma_tf32(float* d, const unsigned* a,
                                         unsigned b0, unsigned b1) {
    asm volatile(
        "mma.sync.aligned.m16n8k8.row.col.f32.tf32.tf32.f32 "
        "{%0,%1,%2,%3}, {%4,%5,%6,%7}, {%8,%9}, {%0,%1,%2,%3};"
        : "+f"(d[0]), "+f"(d[1]), "+f"(d[2]), "+f"(d[3])
        : "r"(a[0]), "r"(a[1]), "r"(a[2]), "r"(a[3]), "r"(b0), "r"(b1));
}

// ---------------------------------------------------------------------------
// Kernel 0: weight prep (w2 -> mma B-frag order; off_w2 parity-split).
// ---------------------------------------------------------------------------
__global__ void k_prep(const float* __restrict__ w2,
                       const float* __restrict__ off_w2) {
    int i = blockIdx.x * blockDim.x + threadIdx.x;
    if (i < 36 * 8 * 32) {
        int kstep = i >> 8;
        int rem   = i & 255;
        int nt    = rem >> 5;
        int lane  = rem & 31;
        int n = nt * 8 + (lane >> 2);
#pragma unroll
        for (int j = 0; j < 2; j++) {
            int k = kstep * 8 + (lane & 3) + 4 * j;
            float w = w2[n * 288 + (k & 31) * 9 + (k >> 5)];
            g_w2m[i * 2 + j] = __uint_as_float(tf32r(w));
        }
    } else {
        int j2 = i - 36 * 8 * 32;
        if (j2 < 288 * 24) {
            int k = j2 / 24, q = j2 % 24;
            int sub = q / 12, j = q % 12;
            int tt = k / 32, ci = k % 32;
            int c = 2 * j + sub;
            g_ow2s[j2] = (j < 9) ? off_w2[(c * 32 + ci) * 9 + tt] : 0.f;
        }
    }
}

// ---------------------------------------------------------------------------
// Kernel 1: fused offset-conv(1->18) + deform-conv(1->32) + relu + maxpool2.
// ---------------------------------------------------------------------------
__global__ void __launch_bounds__(128)
k_stage1(const float* __restrict__ x,
         const float* __restrict__ ow, const float* __restrict__ ob,
         const float* __restrict__ w1, const float* __restrict__ b1, int B) {
    __shared__ float ows[162], w1s[288], obs[18], b1s[32];
    {
        int t = threadIdx.x;
        for (int i = t; i < 162; i += 128) ows[i] = ow[i];
        for (int i = t; i < 288; i += 128) w1s[i] = w1[i];
        if (t < 18) obs[t] = ob[t];
        if (t >= 32 && t < 64) b1s[t - 32] = b1[t - 32];
    }
    __syncthreads();

    int idx  = blockIdx.x * blockDim.x + threadIdx.x;
    int quad = idx & 3;
    int pix  = idx >> 2;
    int npix = B * 196;
    bool valid = pix < npix;
    if (!valid) pix = npix - 1;
    int w2i = pix % 14;
    int t   = pix / 14;
    int h2i = t % 14;
    int b   = t / 14;
    int h = h2i * 2 + (quad >> 1), w = w2i * 2 + (quad & 1);
    const float* xb = x + b * 784;

    float xp[9];
#pragma unroll
    for (int tt = 0; tt < 9; tt++) {
        int yy = h + tt / 3 - 1, xx = w + tt % 3 - 1;
        xp[tt] = (yy >= 0 && yy < 28 && xx >= 0 && xx < 28) ? xb[yy * 28 + xx] : 0.f;
    }

    float samp[9];
#pragma unroll
    for (int kk = 0; kk < 9; kk++) {
        float dy = obs[2 * kk], dx = obs[2 * kk + 1];
#pragma unroll
        for (int tt = 0; tt < 9; tt++) {
            dy = fmaf(ows[(2 * kk) * 9 + tt],     xp[tt], dy);
            dx = fmaf(ows[(2 * kk + 1) * 9 + tt], xp[tt], dx);
        }
        float py = (float)(h + kk / 3 - 1) + dy;
        float px = (float)(w + kk % 3 - 1) + dx;
        float fy = floorf(py), fx = floorf(px);
        float ay = py - fy, ax = px - fx;
        int y0 = (int)fy, x0 = (int)fx;
        float v00 = corner(xb, y0,     x0,     28, 28, 1);
        float v01 = corner(xb, y0,     x0 + 1, 28, 28, 1);
        float v10 = corner(xb, y0 + 1, x0,     28, 28, 1);
        float v11 = corner(xb, y0 + 1, x0 + 1, 28, 28, 1);
        samp[kk] = (1.f - ay) * ((1.f - ax) * v00 + ax * v01)
                 +         ay * ((1.f - ax) * v10 + ax * v11);
    }

    float* o = g_p1t + pix * 32;
#pragma unroll
    for (int oc = 0; oc < 32; oc++) {
        float a = b1s[oc];
#pragma unroll
        for (int kk = 0; kk < 9; kk++) a = fmaf(w1s[oc * 9 + kk], samp[kk], a);
        a = fmaxf(a, __shfl_xor_sync(0xffffffffu, a, 1));
        a = fmaxf(a, __shfl_xor_sync(0xffffffffu, a, 2));
        if (quad == 0 && valid) o[oc] = fmaxf(a, 0.f);
    }
}

// ---------------------------------------------------------------------------
// Kernel 2: offset conv 2 (32 -> 18) + record epilogue (IMAGE-LOCAL offsets).
// ---------------------------------------------------------------------------
__global__ void __launch_bounds__(128)
k_offconv2(const float* __restrict__ ob, int B) {
    int idx = blockIdx.x * blockDim.x + threadIdx.x;
    int sub = idx & 1;
    int pix = idx >> 1;
    int npix = B * 196;
    bool valid = pix < npix;
    if (!valid) pix = npix - 1;
    int w = pix % 14;
    int t = pix / 14;
    int h = t % 14;
    int b = t / 14;

    float acc[9];
#pragma unroll
    for (int c = 0; c < 9; c++) acc[c] = 0.f;

    const float* pb = g_p1t + b * 6272;
    const float* wsub = g_ow2s + sub * 12;

    for (int tt = 0; tt < 9; tt++) {
        int y  = h + tt / 3 - 1;
        int xx = w + tt % 3 - 1;
        if ((unsigned)y >= 14u || (unsigned)xx >= 14u) continue;
        const float* p0 = pb + (y * 14 + xx) * 32;

#pragma unroll
        for (int cib = 0; cib < 4; cib++) {
            float4 va = *(const float4*)(p0 + cib * 8);
            float4 vb = *(const float4*)(p0 + cib * 8 + 4);
            float v[8] = {va.x, va.y, va.z, va.w, vb.x, vb.y, vb.z, vb.w};
#pragma unroll
            for (int q = 0; q < 8; q++) {
                const float* wr = wsub + (tt * 32 + cib * 8 + q) * 24;
                float4 w0 = *(const float4*)(wr);
                float4 w1v = *(const float4*)(wr + 4);
                float4 w2v = *(const float4*)(wr + 8);
                float vv = v[q];
                acc[0] = fmaf(w0.x,  vv, acc[0]);
                acc[1] = fmaf(w0.y,  vv, acc[1]);
                acc[2] = fmaf(w0.z,  vv, acc[2]);
                acc[3] = fmaf(w0.w,  vv, acc[3]);
                acc[4] = fmaf(w1v.x, vv, acc[4]);
                acc[5] = fmaf(w1v.y, vv, acc[5]);
                acc[6] = fmaf(w1v.z, vv, acc[6]);
                acc[7] = fmaf(w1v.w, vv, acc[7]);
                acc[8] = fmaf(w2v.x, vv, acc[8]);
            }
        }
    }

#pragma unroll
    for (int kk = 0; kk < 9; kk++) acc[kk] += ob[2 * kk + sub];

    float dxv[9];
#pragma unroll
    for (int kk = 0; kk < 9; kk++) dxv[kk] = __shfl_xor_sync(0xffffffffu, acc[kk], 1);

    if (sub == 0 && valid) {
        int ri = pix * 9;
#pragma unroll
        for (int kk = 0; kk < 9; kk++) {
            float dy = acc[kk];
            float dx = dxv[kk];
            float py = (float)(h + kk / 3 - 1) + dy;
            float px = (float)(w + kk % 3 - 1) + dx;
            float fy = floorf(py), fx = floorf(px);
            float ay = py - fy, ax = px - fx;
            int y0 = (int)fy, x0i = (int)fx;
            int y1 = y0 + 1,  x1i = x0i + 1;
            float vy0 = (y0  >= 0 && y0  < 14) ? 1.f : 0.f;
            float vy1 = (y1  >= 0 && y1  < 14) ? 1.f : 0.f;
            float vx0 = (x0i >= 0 && x0i < 14) ? 1.f : 0.f;
            float vx1 = (x1i >= 0 && x1i < 14) ? 1.f : 0.f;
            int yc0 = min(max(y0, 0), 13),  yc1 = min(max(y1, 0), 13);
            int xc0 = min(max(x0i, 0), 13), xc1 = min(max(x1i, 0), 13);
            g_recI[ri + kk] = make_int4((yc0 * 14 + xc0) * 32,
                                        (yc0 * 14 + xc1) * 32,
                                        (yc1 * 14 + xc0) * 32,
                                        (yc1 * 14 + xc1) * 32);
            g_recW[ri + kk] = make_float4((1.f - ay) * (1.f - ax) * vy0 * vx0,
                                          (1.f - ay) * ax         * vy0 * vx1,
                                          ay * (1.f - ax)         * vy1 * vx0,
                                          ay * ax                 * vy1 * vx1);
        }
    }
}

// ---------------------------------------------------------------------------
// Kernel 4: deform conv 2 (K=288 -> N=64) + relu + maxpool2 — tensor core,
// GATHER FROM SMEM. Block = 7 pooled pixels of ONE image (grid = B*7, no
// partial blocks). The whole 25KB p1 image is staged in smem once, so every
// bilinear corner load is a 29-cyc conflict-free LDS instead of a 234-cyc L2
// LDG. M=28 rows (pad to 32 with zeros). tf32 mma m16n8k8 as in round 12.
// ---------------------------------------------------------------------------
#define SROW3 37
__global__ void __launch_bounds__(128)
k_deform2(const float* __restrict__ b2, int B) {
    __shared__ float  sImg[6272];             // 25088 B: one p1 image
    __shared__ float  samp[96 * SROW3];       // 14208 B
    __shared__ int4   srecI[252];             // 4032 B
    __shared__ float4 srecW[252];             // 4032 B
    __shared__ int    recbase[28];
    int tid  = threadIdx.x;
    int b = blockIdx.x / 7;
    int g = blockIdx.x % 7;
    int wid = tid >> 5, lane = tid & 31;

    if (tid < 28) {
        int pl = tid >> 2, q = tid & 3;
        int s = g * 7 + pl;
        int h3 = s / 7, w3 = s - h3 * 7;
        int h = h3 * 2 + (q >> 1), w = w3 * 2 + (q & 1);
        recbase[tid] = (b * 196 + h * 14 + w) * 9;
    }
    // zero pad columns m=28..31 (persist across chunks; only m<28 rewritten)
    for (int t = tid; t < 96 * 4; t += 128) {
        int row = t >> 2, m = 28 + (t & 3);
        samp[row * SROW3 + m] = 0.f;
    }
    __syncthreads();

    // stage records (broadcast-ish, independent) and the image (coalesced)
    for (int t = tid; t < 252; t += 128) {
        int m = t / 9, kk = t - m * 9;
        int rb = recbase[m] + kk;
        srecI[t] = g_recI[rb];
        srecW[t] = g_recW[rb];
    }
    {
        const float4* src = (const float4*)(g_p1t + b * 6272);
        float4* dst = (float4*)sImg;
        for (int t = tid; t < 1568; t += 128) dst[t] = src[t];
    }

    float acc[2][2][4];
#pragma unroll
    for (int a = 0; a < 2; a++)
#pragma unroll
        for (int bq = 0; bq < 2; bq++)
#pragma unroll
            for (int j = 0; j < 4; j++) acc[a][bq][j] = 0.f;

    int r0  = lane >> 2;
    int tig = lane & 3;

    for (int c = 0; c < 3; c++) {
        __syncthreads();              // staging done / samp free for rewrite

        // ---- gather: 96 k-rows x 28 m, all from smem ----
#pragma unroll 7
        for (int i = 0; i < 21; i++) {
            int u  = i * 4 + wid;     // 0..83
            int kl = u / 28;
            int m  = u - kl * 28;
            int r  = m * 9 + c * 3 + kl;
            int4   o  = srecI[r];
            float4 rw = srecW[r];
            float val = rw.x * sImg[o.x + lane]
                      + rw.y * sImg[o.y + lane]
                      + rw.z * sImg[o.z + lane]
                      + rw.w * sImg[o.w + lane];
            samp[(kl * 32 + lane) * SROW3 + m] = __uint_as_float(tf32r(val));
        }
        __syncthreads();

        // ---- GEMM slice: 12 ksteps of k8, tf32 mma ----
#pragma unroll 4
        for (int s = 0; s < 12; s++) {
            int krow = s * 8;
            unsigned a0[4], a1[4];
            const float* sa = samp + (krow + tig) * SROW3 + r0;
            const float* sb = samp + (krow + tig + 4) * SROW3 + r0;
            a0[0] = __float_as_uint(sa[0]);
            a0[1] = __float_as_uint(sa[8]);
            a0[2] = __float_as_uint(sb[0]);
            a0[3] = __float_as_uint(sb[8]);
            a1[0] = __float_as_uint(sa[16]);
            a1[1] = __float_as_uint(sa[24]);
            a1[2] = __float_as_uint(sb[16]);
            a1[3] = __float_as_uint(sb[24]);

            int kstep = c * 12 + s;
            const float2* wb = (const float2*)g_w2m
                             + ((kstep * 8 + wid * 2) * 32 + lane);
            float2 bv0 = wb[0];
            float2 bv1 = wb[32];
            unsigned b00 = __float_as_uint(bv0.x), b01 = __float_as_uint(bv0.y);
            unsigned b10 = __float_as_uint(bv1.x), b11 = __float_as_uint(bv1.y);

            mma_tf32(acc[0][0], a0, b00, b01);
            mma_tf32(acc[1][0], a1, b00, b01);
            mma_tf32(acc[0][1], a0, b10, b11);
            mma_tf32(acc[1][1], a1, b10, b11);
        }
    }

    // ---- epilogue: pool over quadrant rows (shfl_xor 4,8), bias, relu ----
#pragma unroll
    for (int mt = 0; mt < 2; mt++) {
#pragma unroll
        for (int nt = 0; nt < 2; nt++) {
            float* d = acc[mt][nt];
#pragma unroll
            for (int j = 0; j < 4; j++) {
                d[j] = fmaxf(d[j], __shfl_xor_sync(0xffffffffu, d[j], 4));
                d[j] = fmaxf(d[j], __shfl_xor_sync(0xffffffffu, d[j], 8));
            }
        }
    }

    if ((r0 & 3) == 0) {              // lanes 0-3 and 16-19 write
        int n0 = wid * 16 + tig * 2;
#pragma unroll
        for (int mt = 0; mt < 2; mt++) {
#pragma unroll
            for (int half = 0; half < 2; half++) {
                int pixl = mt * 4 + half * 2 + (r0 >> 2);
                if (pixl < 7) {
                    int s = g * 7 + pixl;
                    int h3 = s / 7, w3 = s - h3 * 7;
                    float* o = g_p2 + b * 3136 + h3 * 7 + w3;
#pragma unroll
                    for (int nt = 0; nt < 2; nt++) {
                        int n = n0 + nt * 8;
                        float v0 = acc[mt][nt][half * 2];
                        float v1 = acc[mt][nt][half * 2 + 1];
                        o[n * 49]       = fmaxf(v0 + b2[n], 0.f);
                        o[(n + 1) * 49] = fmaxf(v1 + b2[n + 1], 0.f);
                    }
                }
            }
        }
    }
}

// ---------------------------------------------------------------------------
// Kernel 5: FC (B,3136) @ (10,3136)^T + bias. One warp per (b, oc), unrolled.
// ---------------------------------------------------------------------------
__global__ void __launch_bounds__(320)
k_fc(const float* __restrict__ fw, const float* __restrict__ fb,
     float* __restrict__ out, int B) {
    int b = blockIdx.x;
    int warp = threadIdx.x >> 5;
    int lane = threadIdx.x & 31;
    const float* row = g_p2 + b * 3136;
    const float* wr  = fw + warp * 3136;
    float s = 0.f;
    int i = lane * 4;
#pragma unroll 4
    for (int it = 0; it < 24; it++, i += 128) {
        float4 a = *(const float4*)(row + i);
        float4 w = *(const float4*)(wr + i);
        s = fmaf(a.x, w.x, s); s = fmaf(a.y, w.y, s);
        s = fmaf(a.z, w.z, s); s = fmaf(a.w, w.w, s);
    }
    if (i < 3136) {
        float4 a = *(const float4*)(row + i);
        float4 w = *(const float4*)(wr + i);
        s = fmaf(a.x, w.x, s); s = fmaf(a.y, w.y, s);
        s = fmaf(a.z, w.z, s); s = fmaf(a.w, w.w, s);
    }
#pragma unroll
    for (int off = 16; off; off >>= 1) s += __shfl_xor_sync(0xffffffffu, s, off);
    if (lane == 0) out[b * 10 + warp] = s + fb[warp];
}

// ---------------------------------------------------------------------------
extern "C" void kernel_launch(void* const* d_in, const int* in_sizes, int n_in,
                              void* d_out, int out_size) {
    const float* x      = (const float*)d_in[0];
    const float* off_w1 = (const float*)d_in[1];
    const float* off_b1 = (const float*)d_in[2];
    const float* w1     = (const float*)d_in[3];
    const float* b1     = (const float*)d_in[4];
    const float* off_w2 = (const float*)d_in[5];
    const float* off_b2 = (const float*)d_in[6];
    const float* w2     = (const float*)d_in[7];
    const float* b2     = (const float*)d_in[8];
    const float* fc_w   = (const float*)d_in[9];
    const float* fc_b   = (const float*)d_in[10];
    float* out = (float*)d_out;

    int B = in_sizes[0] / 784;
    if (B > BMAX) B = BMAX;

    k_prep<<<(36 * 8 * 32 + 288 * 24 + 255) / 256, 256>>>(w2, off_w2);
    k_stage1<<<(B * 784 + 127) / 128, 128>>>(x, off_w1, off_b1, w1, b1, B);
    k_offconv2<<<(B * 392 + 127) / 128, 128>>>(off_b2, B);
    k_deform2<<<B * 7, 128>>>(b2, B);
    k_fc<<<B, 320>>>(fc_w, fc_b, out, B);
}

// round 15
// speedup vs baseline: 1.0747x; 1.0747x over previous
#include <cuda_runtime.h>
#include <cuda_bf16.h>

#define BMAX 256

// scratch
__device__ float g_p1t [BMAX * 14 * 14 * 32];    // (b, h, w, c) channel-last
__device__ float g_w2m [36 * 8 * 32 * 2];        // mma B-fragment order, tf32-rounded
__device__ float g_ow2s[288 * 24];               // [k=tt*32+ci][sub*12+j], c=2j+sub
__device__ float g_p2  [BMAX * 64 * 7 * 7];      // (b, c, h, w)
__device__ int4   g_recI[BMAX * 196 * 9];        // 4 clamped BATCH-FOLDED gather offsets
__device__ float4 g_recW[BMAX * 196 * 9];        // 4 bilinear weights (0 if invalid)

__device__ __forceinline__ float corner(const float* __restrict__ p,
                                        int y, int x, int H, int W, int stride) {
    bool v = (y >= 0) & (y < H) & (x >= 0) & (x < W);
    int yc = min(max(y, 0), H - 1);
    int xc = min(max(x, 0), W - 1);
    return v ? p[(yc * W + xc) * stride] : 0.f;
}

__device__ __forceinline__ unsigned tf32r(float x) {
    unsigned u;
    asm("cvt.rna.tf32.f32 %0, %1;" : "=r"(u) : "f"(x));
    return u;
}

__device__ __forceinline__ void mma_tf32(float* d, const unsigned* a,
                                         unsigned b0, unsigned b1) {
    asm volatile(
        "mma.sync.aligned.m16n8k8.row.col.f32.tf32.tf32.f32 "
        "{%0,%1,%2,%3}, {%4,%5,%6,%7}, {%8,%9}, {%0,%1,%2,%3};"
        : "+f"(d[0]), "+f"(d[1]), "+f"(d[2]), "+f"(d[3])
        : "r"(a[0]), "r"(a[1]), "r"(a[2]), "r"(a[3]), "r"(b0), "r"(b1));
}

// ---------------------------------------------------------------------------
// Kernel 0: weight prep (w2 -> mma B-frag order; off_w2 parity-split).
// ---------------------------------------------------------------------------
__global__ void k_prep(const float* __restrict__ w2,
                       const float* __restrict__ off_w2) {
    int i = blockIdx.x * blockDim.x + threadIdx.x;
    if (i < 36 * 8 * 32) {
        int kstep = i >> 8;
        int rem   = i & 255;
        int nt    = rem >> 5;
        int lane  = rem & 31;
        int n = nt * 8 + (lane >> 2);
#pragma unroll
        for (int j = 0; j < 2; j++) {
            int k = kstep * 8 + (lane & 3) + 4 * j;
            float w = w2[n * 288 + (k & 31) * 9 + (k >> 5)];
            g_w2m[i * 2 + j] = __uint_as_float(tf32r(w));
        }
    } else {
        int j2 = i - 36 * 8 * 32;
        if (j2 < 288 * 24) {
            int k = j2 / 24, q = j2 % 24;
            int sub = q / 12, j = q % 12;
            int tt = k / 32, ci = k % 32;
            int c = 2 * j + sub;
            g_ow2s[j2] = (j < 9) ? off_w2[(c * 32 + ci) * 9 + tt] : 0.f;
        }
    }
}

// ---------------------------------------------------------------------------
// Kernel 1: fused offset-conv(1->18) + deform-conv(1->32) + relu + maxpool2.
// ---------------------------------------------------------------------------
__global__ void __launch_bounds__(128)
k_stage1(const float* __restrict__ x,
         const float* __restrict__ ow, const float* __restrict__ ob,
         const float* __restrict__ w1, const float* __restrict__ b1, int B) {
    __shared__ float ows[162], w1s[288], obs[18], b1s[32];
    {
        int t = threadIdx.x;
        for (int i = t; i < 162; i += 128) ows[i] = ow[i];
        for (int i = t; i < 288; i += 128) w1s[i] = w1[i];
        if (t < 18) obs[t] = ob[t];
        if (t >= 32 && t < 64) b1s[t - 32] = b1[t - 32];
    }
    __syncthreads();

    int idx  = blockIdx.x * blockDim.x + threadIdx.x;
    int quad = idx & 3;
    int pix  = idx >> 2;
    int npix = B * 196;
    bool valid = pix < npix;
    if (!valid) pix = npix - 1;
    int w2i = pix % 14;
    int t   = pix / 14;
    int h2i = t % 14;
    int b   = t / 14;
    int h = h2i * 2 + (quad >> 1), w = w2i * 2 + (quad & 1);
    const float* xb = x + b * 784;

    float xp[9];
#pragma unroll
    for (int tt = 0; tt < 9; tt++) {
        int yy = h + tt / 3 - 1, xx = w + tt % 3 - 1;
        xp[tt] = (yy >= 0 && yy < 28 && xx >= 0 && xx < 28) ? xb[yy * 28 + xx] : 0.f;
    }

    float samp[9];
#pragma unroll
    for (int kk = 0; kk < 9; kk++) {
        float dy = obs[2 * kk], dx = obs[2 * kk + 1];
#pragma unroll
        for (int tt = 0; tt < 9; tt++) {
            dy = fmaf(ows[(2 * kk) * 9 + tt],     xp[tt], dy);
            dx = fmaf(ows[(2 * kk + 1) * 9 + tt], xp[tt], dx);
        }
        float py = (float)(h + kk / 3 - 1) + dy;
        float px = (float)(w + kk % 3 - 1) + dx;
        float fy = floorf(py), fx = floorf(px);
        float ay = py - fy, ax = px - fx;
        int y0 = (int)fy, x0 = (int)fx;
        float v00 = corner(xb, y0,     x0,     28, 28, 1);
        float v01 = corner(xb, y0,     x0 + 1, 28, 28, 1);
        float v10 = corner(xb, y0 + 1, x0,     28, 28, 1);
        float v11 = corner(xb, y0 + 1, x0 + 1, 28, 28, 1);
        samp[kk] = (1.f - ay) * ((1.f - ax) * v00 + ax * v01)
                 +         ay * ((1.f - ax) * v10 + ax * v11);
    }

    float* o = g_p1t + pix * 32;
#pragma unroll
    for (int oc = 0; oc < 32; oc++) {
        float a = b1s[oc];
#pragma unroll
        for (int kk = 0; kk < 9; kk++) a = fmaf(w1s[oc * 9 + kk], samp[kk], a);
        a = fmaxf(a, __shfl_xor_sync(0xffffffffu, a, 1));
        a = fmaxf(a, __shfl_xor_sync(0xffffffffu, a, 2));
        if (quad == 0 && valid) o[oc] = fmaxf(a, 0.f);
    }
}

// ---------------------------------------------------------------------------
// Kernel 2: offset conv 2 (32 -> 18) + record epilogue (batch-folded offsets).
// ---------------------------------------------------------------------------
__global__ void __launch_bounds__(128)
k_offconv2(const float* __restrict__ ob, int B) {
    int idx = blockIdx.x * blockDim.x + threadIdx.x;
    int sub = idx & 1;
    int pix = idx >> 1;
    int npix = B * 196;
    bool valid = pix < npix;
    if (!valid) pix = npix - 1;
    int w = pix % 14;
    int t = pix / 14;
    int h = t % 14;
    int b = t / 14;

    float acc[9];
#pragma unroll
    for (int c = 0; c < 9; c++) acc[c] = 0.f;

    const float* pb = g_p1t + b * 6272;
    const float* wsub = g_ow2s + sub * 12;

    for (int tt = 0; tt < 9; tt++) {
        int y  = h + tt / 3 - 1;
        int xx = w + tt % 3 - 1;
        if ((unsigned)y >= 14u || (unsigned)xx >= 14u) continue;
        const float* p0 = pb + (y * 14 + xx) * 32;

#pragma unroll
        for (int cib = 0; cib < 4; cib++) {
            float4 va = *(const float4*)(p0 + cib * 8);
            float4 vb = *(const float4*)(p0 + cib * 8 + 4);
            float v[8] = {va.x, va.y, va.z, va.w, vb.x, vb.y, vb.z, vb.w};
#pragma unroll
            for (int q = 0; q < 8; q++) {
                const float* wr = wsub + (tt * 32 + cib * 8 + q) * 24;
                float4 w0 = *(const float4*)(wr);
                float4 w1v = *(const float4*)(wr + 4);
                float4 w2v = *(const float4*)(wr + 8);
                float vv = v[q];
                acc[0] = fmaf(w0.x,  vv, acc[0]);
                acc[1] = fmaf(w0.y,  vv, acc[1]);
                acc[2] = fmaf(w0.z,  vv, acc[2]);
                acc[3] = fmaf(w0.w,  vv, acc[3]);
                acc[4] = fmaf(w1v.x, vv, acc[4]);
                acc[5] = fmaf(w1v.y, vv, acc[5]);
                acc[6] = fmaf(w1v.z, vv, acc[6]);
                acc[7] = fmaf(w1v.w, vv, acc[7]);
                acc[8] = fmaf(w2v.x, vv, acc[8]);
            }
        }
    }

#pragma unroll
    for (int kk = 0; kk < 9; kk++) acc[kk] += ob[2 * kk + sub];

    float dxv[9];
#pragma unroll
    for (int kk = 0; kk < 9; kk++) dxv[kk] = __shfl_xor_sync(0xffffffffu, acc[kk], 1);

    if (sub == 0 && valid) {
        int bbase = b * 6272;
        int ri = pix * 9;
#pragma unroll
        for (int kk = 0; kk < 9; kk++) {
            float dy = acc[kk];
            float dx = dxv[kk];
            float py = (float)(h + kk / 3 - 1) + dy;
            float px = (float)(w + kk % 3 - 1) + dx;
            float fy = floorf(py), fx = floorf(px);
            float ay = py - fy, ax = px - fx;
            int y0 = (int)fy, x0i = (int)fx;
            int y1 = y0 + 1,  x1i = x0i + 1;
            float vy0 = (y0  >= 0 && y0  < 14) ? 1.f : 0.f;
            float vy1 = (y1  >= 0 && y1  < 14) ? 1.f : 0.f;
            float vx0 = (x0i >= 0 && x0i < 14) ? 1.f : 0.f;
            float vx1 = (x1i >= 0 && x1i < 14) ? 1.f : 0.f;
            int yc0 = min(max(y0, 0), 13),  yc1 = min(max(y1, 0), 13);
            int xc0 = min(max(x0i, 0), 13), xc1 = min(max(x1i, 0), 13);
            g_recI[ri + kk] = make_int4(bbase + (yc0 * 14 + xc0) * 32,
                                        bbase + (yc0 * 14 + xc1) * 32,
                                        bbase + (yc1 * 14 + xc0) * 32,
                                        bbase + (yc1 * 14 + xc1) * 32);
            g_recW[ri + kk] = make_float4((1.f - ay) * (1.f - ax) * vy0 * vx0,
                                          (1.f - ay) * ax         * vy0 * vx1,
                                          ay * (1.f - ax)         * vy1 * vx0,
                                          ay * ax                 * vy1 * vx1);
        }
    }
}

// ---------------------------------------------------------------------------
// Kernel 4: deform conv 2 (K=288 -> N=64) + relu + maxpool2 — tensor core.
// QUARTER blocks: 4 pixels (M=16), 128 threads, smem 11.2KB -> ~2x occupancy
// vs the M=32 version. Record-driven L2 gathers fill samp[k][m] (SROW=17
// conflict-free), tf32 mma m16n8k8, pool/bias/relu in epilogue.
// ---------------------------------------------------------------------------
#define SROW4 17
__global__ void __launch_bounds__(128)
k_deform2(const float* __restrict__ b2, int B) {
    __shared__ float  samp[96 * SROW4];       // 6528 B
    __shared__ int4   srecI[144];             // 2304 B
    __shared__ float4 srecW[144];             // 2304 B
    __shared__ int    recbase[16];
    int tid  = threadIdx.x;
    int pix0 = blockIdx.x * 4;
    int npix = B * 49;
    int wid = tid >> 5, lane = tid & 31;

    if (tid < 16) {
        int pl = tid >> 2, q = tid & 3;
        int pix = pix0 + pl;
        int rb = -1;
        if (pix < npix) {
            int b  = pix / 49;
            int s  = pix - b * 49;
            int h3 = s / 7, w3 = s - h3 * 7;
            int h  = h3 * 2 + (q >> 1), w = w3 * 2 + (q & 1);
            rb = (b * 196 + h * 14 + w) * 9;
        }
        recbase[tid] = rb;
    }
    __syncthreads();

    // batch record prefetch: ALL 144 records (strided — 128 threads < 144!)
    for (int t = tid; t < 144; t += 128) {
        int m = t / 9, kk = t - m * 9;
        int rb = recbase[m];
        if (rb >= 0) {
            srecI[t] = g_recI[rb + kk];
            srecW[t] = g_recW[rb + kk];
        } else {
            srecI[t] = make_int4(0, 0, 0, 0);
            srecW[t] = make_float4(0.f, 0.f, 0.f, 0.f);
        }
    }

    float acc[2][4];                  // [ntile][frag]
#pragma unroll
    for (int bq = 0; bq < 2; bq++)
#pragma unroll
        for (int j = 0; j < 4; j++) acc[bq][j] = 0.f;

    int r0  = lane >> 2;
    int tig = lane & 3;

    for (int c = 0; c < 3; c++) {
        __syncthreads();              // srec ready / samp reuse

        // ---- gather: 96 k-rows x 16 m (L2 gathers, records from smem) ----
#pragma unroll 6
        for (int i = 0; i < 12; i++) {
            int u  = i * 4 + wid;     // 0..47
            int kl = u >> 4;          // 0..2
            int m  = u & 15;
            int r  = m * 9 + c * 3 + kl;
            int4   o  = srecI[r];
            float4 rw = srecW[r];
            float val = rw.x * g_p1t[o.x + lane]
                      + rw.y * g_p1t[o.y + lane]
                      + rw.z * g_p1t[o.z + lane]
                      + rw.w * g_p1t[o.w + lane];
            samp[(kl * 32 + lane) * SROW4 + m] = __uint_as_float(tf32r(val));
        }
        __syncthreads();

        // ---- GEMM slice: 12 ksteps of k8, tf32 mma ----
#pragma unroll 4
        for (int s = 0; s < 12; s++) {
            int krow = s * 8;
            unsigned a0[4];
            const float* sa = samp + (krow + tig) * SROW4 + r0;
            const float* sb = samp + (krow + tig + 4) * SROW4 + r0;
            a0[0] = __float_as_uint(sa[0]);
            a0[1] = __float_as_uint(sa[8]);
            a0[2] = __float_as_uint(sb[0]);
            a0[3] = __float_as_uint(sb[8]);

            int kstep = c * 12 + s;
            const float2* wb = (const float2*)g_w2m
                             + ((kstep * 8 + wid * 2) * 32 + lane);
            float2 bv0 = wb[0];
            float2 bv1 = wb[32];
            unsigned b00 = __float_as_uint(bv0.x), b01 = __float_as_uint(bv0.y);
            unsigned b10 = __float_as_uint(bv1.x), b11 = __float_as_uint(bv1.y);

            mma_tf32(acc[0], a0, b00, b01);
            mma_tf32(acc[1], a0, b10, b11);
        }
    }

    // ---- epilogue: pool over quadrant rows (shfl_xor 4,8), bias, relu ----
#pragma unroll
    for (int nt = 0; nt < 2; nt++) {
        float* d = acc[nt];
#pragma unroll
        for (int j = 0; j < 4; j++) {
            d[j] = fmaxf(d[j], __shfl_xor_sync(0xffffffffu, d[j], 4));
            d[j] = fmaxf(d[j], __shfl_xor_sync(0xffffffffu, d[j], 8));
        }
    }

    if ((r0 & 3) == 0) {              // lanes 0-3 and 16-19 write
        int n0 = wid * 16 + tig * 2;
#pragma unroll
        for (int half = 0; half < 2; half++) {    // c0c1 (rows r0) vs c2c3 (r0+8)
            int pixl = half * 2 + (r0 >> 2);
            int pix  = pix0 + pixl;
            if (pix < npix) {
                int b = pix / 49, s = pix - b * 49;
                int h3 = s / 7, w3 = s - h3 * 7;
                float* o = g_p2 + b * 3136 + h3 * 7 + w3;
#pragma unroll
                for (int nt = 0; nt < 2; nt++) {
                    int n = n0 + nt * 8;
                    float v0 = acc[nt][half * 2];
                    float v1 = acc[nt][half * 2 + 1];
                    o[n * 49]       = fmaxf(v0 + b2[n], 0.f);
                    o[(n + 1) * 49] = fmaxf(v1 + b2[n + 1], 0.f);
                }
            }
        }
    }
}

// ---------------------------------------------------------------------------
// Kernel 5: FC (B,3136) @ (10,3136)^T + bias. One warp per (b, oc), unrolled.
// ---------------------------------------------------------------------------
__global__ void __launch_bounds__(320)
k_fc(const float* __restrict__ fw, const float* __restrict__ fb,
     float* __restrict__ out, int B) {
    int b = blockIdx.x;
    int warp = threadIdx.x >> 5;
    int lane = threadIdx.x & 31;
    const float* row = g_p2 + b * 3136;
    const float* wr  = fw + warp * 3136;
    float s = 0.f;
    int i = lane * 4;
#pragma unroll 4
    for (int it = 0; it < 24; it++, i += 128) {
        float4 a = *(const float4*)(row + i);
        float4 w = *(const float4*)(wr + i);
        s = fmaf(a.x, w.x, s); s = fmaf(a.y, w.y, s);
        s = fmaf(a.z, w.z, s); s = fmaf(a.w, w.w, s);
    }
    if (i < 3136) {
        float4 a = *(const float4*)(row + i);
        float4 w = *(const float4*)(wr + i);
        s = fmaf(a.x, w.x, s); s = fmaf(a.y, w.y, s);
        s = fmaf(a.z, w.z, s); s = fmaf(a.w, w.w, s);
    }
#pragma unroll
    for (int off = 16; off; off >>= 1) s += __shfl_xor_sync(0xffffffffu, s, off);
    if (lane == 0) out[b * 10 + warp] = s + fb[warp];
}

// ---------------------------------------------------------------------------
extern "C" void kernel_launch(void* const* d_in, const int* in_sizes, int n_in,
                              void* d_out, int out_size) {
    const float* x      = (const float*)d_in[0];
    const float* off_w1 = (const float*)d_in[1];
    const float* off_b1 = (const float*)d_in[2];
    const float* w1     = (const float*)d_in[3];
    const float* b1     = (const float*)d_in[4];
    const float* off_w2 = (const float*)d_in[5];
    const float* off_b2 = (const float*)d_in[6];
    const float* w2     = (const float*)d_in[7];
    const float* b2     = (const float*)d_in[8];
    const float* fc_w   = (const float*)d_in[9];
    const float* fc_b   = (const float*)d_in[10];
    float* out = (float*)d_out;

    int B = in_sizes[0] / 784;
    if (B > BMAX) B = BMAX;

    k_prep<<<(36 * 8 * 32 + 288 * 24 + 255) / 256, 256>>>(w2, off_w2);
    k_stage1<<<(B * 784 + 127) / 128, 128>>>(x, off_w1, off_b1, w1, b1, B);
    k_offconv2<<<(B * 392 + 127) / 128, 128>>>(off_b2, B);
    k_deform2<<<(B * 49 + 3) / 4, 128>>>(b2, B);
    k_fc<<<B, 320>>>(fc_w, fc_b, out, B);
}

// round 16
// speedup vs baseline: 1.2453x; 1.1587x over previous
#include <cuda_runtime.h>
#include <cuda_bf16.h>

#define BMAX 256

// scratch
__device__ float g_p1t [BMAX * 14 * 14 * 32];    // (b, h, w, c) channel-last
__device__ float g_w2m [36 * 8 * 32 * 2];        // mma B-fragment order, tf32-rounded
__device__ float g_ow2s[288 * 24];               // [k=tt*32+ci][sub*12+j], c=2j+sub
__device__ float g_p2  [BMAX * 64 * 7 * 7];      // (b, c, h, w)
__device__ int4   g_recI[BMAX * 196 * 9];        // 4 clamped BATCH-FOLDED gather offsets
__device__ float4 g_recW[BMAX * 196 * 9];        // 4 bilinear weights (0 if invalid)

__device__ __forceinline__ float corner(const float* __restrict__ p,
                                        int y, int x, int H, int W, int stride) {
    bool v = (y >= 0) & (y < H) & (x >= 0) & (x < W);
    int yc = min(max(y, 0), H - 1);
    int xc = min(max(x, 0), W - 1);
    return v ? p[(yc * W + xc) * stride] : 0.f;
}

__device__ __forceinline__ unsigned tf32r(float x) {
    unsigned u;
    asm("cvt.rna.tf32.f32 %0, %1;" : "=r"(u) : "f"(x));
    return u;
}

__device__ __forceinline__ void mma_tf32(float* d, const unsigned* a,
                                         unsigned b0, unsigned b1) {
    asm volatile(
        "mma.sync.aligned.m16n8k8.row.col.f32.tf32.tf32.f32 "
        "{%0,%1,%2,%3}, {%4,%5,%6,%7}, {%8,%9}, {%0,%1,%2,%3};"
        : "+f"(d[0]), "+f"(d[1]), "+f"(d[2]), "+f"(d[3])
        : "r"(a[0]), "r"(a[1]), "r"(a[2]), "r"(a[3]), "r"(b0), "r"(b1));
}

// ---------------------------------------------------------------------------
// Kernel 0: weight prep (w2 -> mma B-frag order; off_w2 parity-split).
// ---------------------------------------------------------------------------
__global__ void k_prep(const float* __restrict__ w2,
                       const float* __restrict__ off_w2) {
    int i = blockIdx.x * blockDim.x + threadIdx.x;
    if (i < 36 * 8 * 32) {
        int kstep = i >> 8;
        int rem   = i & 255;
        int nt    = rem >> 5;
        int lane  = rem & 31;
        int n = nt * 8 + (lane >> 2);
#pragma unroll
        for (int j = 0; j < 2; j++) {
            int k = kstep * 8 + (lane & 3) + 4 * j;
            float w = w2[n * 288 + (k & 31) * 9 + (k >> 5)];
            g_w2m[i * 2 + j] = __uint_as_float(tf32r(w));
        }
    } else {
        int j2 = i - 36 * 8 * 32;
        if (j2 < 288 * 24) {
            int k = j2 / 24, q = j2 % 24;
            int sub = q / 12, j = q % 12;
            int tt = k / 32, ci = k % 32;
            int c = 2 * j + sub;
            g_ow2s[j2] = (j < 9) ? off_w2[(c * 32 + ci) * 9 + tt] : 0.f;
        }
    }
}

// ---------------------------------------------------------------------------
// Kernel 1: fused offset-conv(1->18) + deform-conv(1->32) + relu + maxpool2.
// ---------------------------------------------------------------------------
__global__ void __launch_bounds__(128)
k_stage1(const float* __restrict__ x,
         const float* __restrict__ ow, const float* __restrict__ ob,
         const float* __restrict__ w1, const float* __restrict__ b1, int B) {
    __shared__ float ows[162], w1s[288], obs[18], b1s[32];
    {
        int t = threadIdx.x;
        for (int i = t; i < 162; i += 128) ows[i] = ow[i];
        for (int i = t; i < 288; i += 128) w1s[i] = w1[i];
        if (t < 18) obs[t] = ob[t];
        if (t >= 32 && t < 64) b1s[t - 32] = b1[t - 32];
    }
    __syncthreads();

    int idx  = blockIdx.x * blockDim.x + threadIdx.x;
    int quad = idx & 3;
    int pix  = idx >> 2;
    int npix = B * 196;
    bool valid = pix < npix;
    if (!valid) pix = npix - 1;
    int w2i = pix % 14;
    int t   = pix / 14;
    int h2i = t % 14;
    int b   = t / 14;
    int h = h2i * 2 + (quad >> 1), w = w2i * 2 + (quad & 1);
    const float* xb = x + b * 784;

    float xp[9];
#pragma unroll
    for (int tt = 0; tt < 9; tt++) {
        int yy = h + tt / 3 - 1, xx = w + tt % 3 - 1;
        xp[tt] = (yy >= 0 && yy < 28 && xx >= 0 && xx < 28) ? xb[yy * 28 + xx] : 0.f;
    }

    float samp[9];
#pragma unroll
    for (int kk = 0; kk < 9; kk++) {
        float dy = obs[2 * kk], dx = obs[2 * kk + 1];
#pragma unroll
        for (int tt = 0; tt < 9; tt++) {
            dy = fmaf(ows[(2 * kk) * 9 + tt],     xp[tt], dy);
            dx = fmaf(ows[(2 * kk + 1) * 9 + tt], xp[tt], dx);
        }
        float py = (float)(h + kk / 3 - 1) + dy;
        float px = (float)(w + kk % 3 - 1) + dx;
        float fy = floorf(py), fx = floorf(px);
        float ay = py - fy, ax = px - fx;
        int y0 = (int)fy, x0 = (int)fx;
        float v00 = corner(xb, y0,     x0,     28, 28, 1);
        float v01 = corner(xb, y0,     x0 + 1, 28, 28, 1);
        float v10 = corner(xb, y0 + 1, x0,     28, 28, 1);
        float v11 = corner(xb, y0 + 1, x0 + 1, 28, 28, 1);
        samp[kk] = (1.f - ay) * ((1.f - ax) * v00 + ax * v01)
                 +         ay * ((1.f - ax) * v10 + ax * v11);
    }

    float* o = g_p1t + pix * 32;
#pragma unroll
    for (int oc = 0; oc < 32; oc++) {
        float a = b1s[oc];
#pragma unroll
        for (int kk = 0; kk < 9; kk++) a = fmaf(w1s[oc * 9 + kk], samp[kk], a);
        a = fmaxf(a, __shfl_xor_sync(0xffffffffu, a, 1));
        a = fmaxf(a, __shfl_xor_sync(0xffffffffu, a, 2));
        if (quad == 0 && valid) o[oc] = fmaxf(a, 0.f);
    }
}

// ---------------------------------------------------------------------------
// Kernel 2: offset conv 2 (32 -> 18) + record epilogue.
// Parity-split (2 threads/pixel) as round 11; weight table STAGED IN SMEM:
// broadcast LDS issues ~3.6x faster per SM than broadcast LDG -> the 864
// uniform weight loads per warp stop being the LSU-issue bottleneck.
// ---------------------------------------------------------------------------
__global__ void __launch_bounds__(128)
k_offconv2(const float* __restrict__ ob, int B) {
    __shared__ float ws[288 * 24];            // 27648 B
    {
        const float4* src = (const float4*)g_ow2s;
        float4* dst = (float4*)ws;
        for (int t = threadIdx.x; t < 288 * 6; t += 128) dst[t] = src[t];
    }
    __syncthreads();

    int idx = blockIdx.x * blockDim.x + threadIdx.x;
    int sub = idx & 1;
    int pix = idx >> 1;
    int npix = B * 196;
    bool valid = pix < npix;
    if (!valid) pix = npix - 1;
    int w = pix % 14;
    int t = pix / 14;
    int h = t % 14;
    int b = t / 14;

    float acc[9];
#pragma unroll
    for (int c = 0; c < 9; c++) acc[c] = 0.f;

    const float* pb = g_p1t + b * 6272;
    const float* wsub = ws + sub * 12;

    for (int tt = 0; tt < 9; tt++) {
        int y  = h + tt / 3 - 1;
        int xx = w + tt % 3 - 1;
        if ((unsigned)y >= 14u || (unsigned)xx >= 14u) continue;
        const float* p0 = pb + (y * 14 + xx) * 32;

#pragma unroll
        for (int cib = 0; cib < 4; cib++) {
            float4 va = *(const float4*)(p0 + cib * 8);
            float4 vb = *(const float4*)(p0 + cib * 8 + 4);
            float v[8] = {va.x, va.y, va.z, va.w, vb.x, vb.y, vb.z, vb.w};
#pragma unroll
            for (int q = 0; q < 8; q++) {
                const float* wr = wsub + (tt * 32 + cib * 8 + q) * 24;
                float4 w0 = *(const float4*)(wr);
                float4 w1v = *(const float4*)(wr + 4);
                float4 w2v = *(const float4*)(wr + 8);
                float vv = v[q];
                acc[0] = fmaf(w0.x,  vv, acc[0]);
                acc[1] = fmaf(w0.y,  vv, acc[1]);
                acc[2] = fmaf(w0.z,  vv, acc[2]);
                acc[3] = fmaf(w0.w,  vv, acc[3]);
                acc[4] = fmaf(w1v.x, vv, acc[4]);
                acc[5] = fmaf(w1v.y, vv, acc[5]);
                acc[6] = fmaf(w1v.z, vv, acc[6]);
                acc[7] = fmaf(w1v.w, vv, acc[7]);
                acc[8] = fmaf(w2v.x, vv, acc[8]);
            }
        }
    }

#pragma unroll
    for (int kk = 0; kk < 9; kk++) acc[kk] += ob[2 * kk + sub];

    float dxv[9];
#pragma unroll
    for (int kk = 0; kk < 9; kk++) dxv[kk] = __shfl_xor_sync(0xffffffffu, acc[kk], 1);

    if (sub == 0 && valid) {
        int bbase = b * 6272;
        int ri = pix * 9;
#pragma unroll
        for (int kk = 0; kk < 9; kk++) {
            float dy = acc[kk];
            float dx = dxv[kk];
            float py = (float)(h + kk / 3 - 1) + dy;
            float px = (float)(w + kk % 3 - 1) + dx;
            float fy = floorf(py), fx = floorf(px);
            float ay = py - fy, ax = px - fx;
            int y0 = (int)fy, x0i = (int)fx;
            int y1 = y0 + 1,  x1i = x0i + 1;
            float vy0 = (y0  >= 0 && y0  < 14) ? 1.f : 0.f;
            float vy1 = (y1  >= 0 && y1  < 14) ? 1.f : 0.f;
            float vx0 = (x0i >= 0 && x0i < 14) ? 1.f : 0.f;
            float vx1 = (x1i >= 0 && x1i < 14) ? 1.f : 0.f;
            int yc0 = min(max(y0, 0), 13),  yc1 = min(max(y1, 0), 13);
            int xc0 = min(max(x0i, 0), 13), xc1 = min(max(x1i, 0), 13);
            g_recI[ri + kk] = make_int4(bbase + (yc0 * 14 + xc0) * 32,
                                        bbase + (yc0 * 14 + xc1) * 32,
                                        bbase + (yc1 * 14 + xc0) * 32,
                                        bbase + (yc1 * 14 + xc1) * 32);
            g_recW[ri + kk] = make_float4((1.f - ay) * (1.f - ax) * vy0 * vx0,
                                          (1.f - ay) * ax         * vy0 * vx1,
                                          ay * (1.f - ax)         * vy1 * vx0,
                                          ay * ax                 * vy1 * vx1);
        }
    }
}

// ---------------------------------------------------------------------------
// Kernel 4: deform conv 2 (K=288 -> N=64) + relu + maxpool2 — tensor core.
// Quarter blocks: 4 pixels (M=16), 128 threads (round-15 version, 54.5us).
// ---------------------------------------------------------------------------
#define SROW4 17
__global__ void __launch_bounds__(128)
k_deform2(const float* __restrict__ b2, int B) {
    __shared__ float  samp[96 * SROW4];       // 6528 B
    __shared__ int4   srecI[144];             // 2304 B
    __shared__ float4 srecW[144];             // 2304 B
    __shared__ int    recbase[16];
    int tid  = threadIdx.x;
    int pix0 = blockIdx.x * 4;
    int npix = B * 49;
    int wid = tid >> 5, lane = tid & 31;

    if (tid < 16) {
        int pl = tid >> 2, q = tid & 3;
        int pix = pix0 + pl;
        int rb = -1;
        if (pix < npix) {
            int b  = pix / 49;
            int s  = pix - b * 49;
            int h3 = s / 7, w3 = s - h3 * 7;
            int h  = h3 * 2 + (q >> 1), w = w3 * 2 + (q & 1);
            rb = (b * 196 + h * 14 + w) * 9;
        }
        recbase[tid] = rb;
    }
    __syncthreads();

    // batch record prefetch: ALL 144 records (strided; 128 threads < 144)
    for (int t = tid; t < 144; t += 128) {
        int m = t / 9, kk = t - m * 9;
        int rb = recbase[m];
        if (rb >= 0) {
            srecI[t] = g_recI[rb + kk];
            srecW[t] = g_recW[rb + kk];
        } else {
            srecI[t] = make_int4(0, 0, 0, 0);
            srecW[t] = make_float4(0.f, 0.f, 0.f, 0.f);
        }
    }

    float acc[2][4];                  // [ntile][frag]
#pragma unroll
    for (int bq = 0; bq < 2; bq++)
#pragma unroll
        for (int j = 0; j < 4; j++) acc[bq][j] = 0.f;

    int r0  = lane >> 2;
    int tig = lane & 3;

    for (int c = 0; c < 3; c++) {
        __syncthreads();              // srec ready / samp reuse

        // ---- gather: 96 k-rows x 16 m (L2 gathers, records from smem) ----
#pragma unroll 6
        for (int i = 0; i < 12; i++) {
            int u  = i * 4 + wid;     // 0..47
            int kl = u >> 4;          // 0..2
            int m  = u & 15;
            int r  = m * 9 + c * 3 + kl;
            int4   o  = srecI[r];
            float4 rw = srecW[r];
            float val = rw.x * g_p1t[o.x + lane]
                      + rw.y * g_p1t[o.y + lane]
                      + rw.z * g_p1t[o.z + lane]
                      + rw.w * g_p1t[o.w + lane];
            samp[(kl * 32 + lane) * SROW4 + m] = __uint_as_float(tf32r(val));
        }
        __syncthreads();

        // ---- GEMM slice: 12 ksteps of k8, tf32 mma ----
#pragma unroll 4
        for (int s = 0; s < 12; s++) {
            int krow = s * 8;
            unsigned a0[4];
            const float* sa = samp + (krow + tig) * SROW4 + r0;
            const float* sb = samp + (krow + tig + 4) * SROW4 + r0;
            a0[0] = __float_as_uint(sa[0]);
            a0[1] = __float_as_uint(sa[8]);
            a0[2] = __float_as_uint(sb[0]);
            a0[3] = __float_as_uint(sb[8]);

            int kstep = c * 12 + s;
            const float2* wb = (const float2*)g_w2m
                             + ((kstep * 8 + wid * 2) * 32 + lane);
            float2 bv0 = wb[0];
            float2 bv1 = wb[32];
            unsigned b00 = __float_as_uint(bv0.x), b01 = __float_as_uint(bv0.y);
            unsigned b10 = __float_as_uint(bv1.x), b11 = __float_as_uint(bv1.y);

            mma_tf32(acc[0], a0, b00, b01);
            mma_tf32(acc[1], a0, b10, b11);
        }
    }

    // ---- epilogue: pool over quadrant rows (shfl_xor 4,8), bias, relu ----
#pragma unroll
    for (int nt = 0; nt < 2; nt++) {
        float* d = acc[nt];
#pragma unroll
        for (int j = 0; j < 4; j++) {
            d[j] = fmaxf(d[j], __shfl_xor_sync(0xffffffffu, d[j], 4));
            d[j] = fmaxf(d[j], __shfl_xor_sync(0xffffffffu, d[j], 8));
        }
    }

    if ((r0 & 3) == 0) {              // lanes 0-3 and 16-19 write
        int n0 = wid * 16 + tig * 2;
#pragma unroll
        for (int half = 0; half < 2; half++) {
            int pixl = half * 2 + (r0 >> 2);
            int pix  = pix0 + pixl;
            if (pix < npix) {
                int b = pix / 49, s = pix - b * 49;
                int h3 = s / 7, w3 = s - h3 * 7;
                float* o = g_p2 + b * 3136 + h3 * 7 + w3;
#pragma unroll
                for (int nt = 0; nt < 2; nt++) {
                    int n = n0 + nt * 8;
                    float v0 = acc[nt][half * 2];
                    float v1 = acc[nt][half * 2 + 1];
                    o[n * 49]       = fmaxf(v0 + b2[n], 0.f);
                    o[(n + 1) * 49] = fmaxf(v1 + b2[n + 1], 0.f);
                }
            }
        }
    }
}

// ---------------------------------------------------------------------------
// Kernel 5: FC (B,3136) @ (10,3136)^T + bias. One warp per (b, oc);
// 4 rotating accumulators break the serial FMA dependency chain.
// ---------------------------------------------------------------------------
__global__ void __launch_bounds__(320)
k_fc(const float* __restrict__ fw, const float* __restrict__ fb,
     float* __restrict__ out, int B) {
    int b = blockIdx.x;
    int warp = threadIdx.x >> 5;
    int lane = threadIdx.x & 31;
    const float* row = g_p2 + b * 3136;
    const float* wr  = fw + warp * 3136;
    float s0 = 0.f, s1 = 0.f, s2 = 0.f, s3 = 0.f;
    int i = lane * 4;
#pragma unroll 4
    for (int it = 0; it < 24; it++, i += 128) {
        float4 a = *(const float4*)(row + i);
        float4 w = *(const float4*)(wr + i);
        float p = fmaf(a.x, w.x, fmaf(a.y, w.y, a.z * w.z + a.w * w.w));
        switch (it & 3) {
            case 0: s0 += p; break;
            case 1: s1 += p; break;
            case 2: s2 += p; break;
            default: s3 += p; break;
        }
    }
    if (i < 3136) {                    // tail: lanes 0..15
        float4 a = *(const float4*)(row + i);
        float4 w = *(const float4*)(wr + i);
        s0 = fmaf(a.x, w.x, s0); s1 = fmaf(a.y, w.y, s1);
        s2 = fmaf(a.z, w.z, s2); s3 = fmaf(a.w, w.w, s3);
    }
    float s = (s0 + s1) + (s2 + s3);
#pragma unroll
    for (int off = 16; off; off >>= 1) s += __shfl_xor_sync(0xffffffffu, s, off);
    if (lane == 0) out[b * 10 + warp] = s + fb[warp];
}

// ---------------------------------------------------------------------------
extern "C" void kernel_launch(void* const* d_in, const int* in_sizes, int n_in,
                              void* d_out, int out_size) {
    const float* x      = (const float*)d_in[0];
    const float* off_w1 = (const float*)d_in[1];
    const float* off_b1 = (const float*)d_in[2];
    const float* w1     = (const float*)d_in[3];
    const float* b1     = (const float*)d_in[4];
    const float* off_w2 = (const float*)d_in[5];
    const float* off_b2 = (const float*)d_in[6];
    const float* w2     = (const float*)d_in[7];
    const float* b2     = (const float*)d_in[8];
    const float* fc_w   = (const float*)d_in[9];
    const float* fc_b   = (const float*)d_in[10];
    float* out = (float*)d_out;

    int B = in_sizes[0] / 784;
    if (B > BMAX) B = BMAX;

    k_prep<<<(36 * 8 * 32 + 288 * 24 + 255) / 256, 256>>>(w2, off_w2);
    k_stage1<<<(B * 784 + 127) / 128, 128>>>(x, off_w1, off_b1, w1, b1, B);
    k_offconv2<<<(B * 392 + 127) / 128, 128>>>(off_b2, B);
    k_deform2<<<(B * 49 + 3) / 4, 128>>>(b2, B);
    k_fc<<<B, 320>>>(fc_w, fc_b, out, B);
}